// round 6
// baseline (speedup 1.0000x reference)
#include <cuda_runtime.h>
#include <cuda_bf16.h>

// ---------------------------------------------------------------------------
// HeteroRGCN layer, atomic-free CSR formulation:
//   mean_dst(W x_src + b) = W * mean_dst(x_src) + b   (b masked where deg==0)
// 6 launches:
//   1. zero counters              2. histogram dst degrees (both relations)
//   3. scan phase 1 (per-block)   4. scan phase 2 (add block-prefix, init cursor)
//   5. reorder edges by dst       6. FUSED segment-mean + Linear -> d_out
// ---------------------------------------------------------------------------

#define MAXN 100000
#define MAXE 1000000
#define SCAN_B 256
#define NODES_PER_BLK 64

// rel 1 (clicks): dst = items.   rel 2 (clicked_by): dst = users.
__device__ int g_off1[MAXN + 1];
__device__ int g_off2[MAXN + 1];
__device__ int g_cur1[MAXN + 1];
__device__ int g_cur2[MAXN + 1];
__device__ int g_csr1[MAXE];
__device__ int g_csr2[MAXE];
__device__ int g_bsum1[512];
__device__ int g_bsum2[512];

// ---------------------------------------------------------------------------
__global__ void zero_cnt(int n1, int n2) {
    int i = blockIdx.x * blockDim.x + threadIdx.x;
    if (i <= n1) g_off1[i] = 0;
    if (i <= n2) g_off2[i] = 0;
}

__global__ void hist_kernel(const int* __restrict__ dst1, int E1,
                            const int* __restrict__ dst2, int E2) {
    int i = blockIdx.x * blockDim.x + threadIdx.x;
    if (i < E1) atomicAdd(&g_off1[__ldg(dst1 + i) + 1], 1);
    if (i < E2) atomicAdd(&g_off2[__ldg(dst2 + i) + 1], 1);
}

// Scan phase 1: per-block inclusive scan + block sums. Both relations.
__global__ void scan_block(int nb1, int n1, int n2) {
    __shared__ int s[SCAN_B];
    int sel = (blockIdx.x >= nb1) ? 1 : 0;
    int blk = sel ? blockIdx.x - nb1 : blockIdx.x;
    int n   = sel ? n2 : n1;
    int* data = sel ? g_off2 : g_off1;
    int* bsum = sel ? g_bsum2 : g_bsum1;

    int t = threadIdx.x;
    int i = blk * SCAN_B + t;
    s[t] = (i < n) ? data[i] : 0;
    __syncthreads();
#pragma unroll
    for (int d = 1; d < SCAN_B; d <<= 1) {
        int x = (t >= d) ? s[t - d] : 0;
        __syncthreads();
        s[t] += x;
        __syncthreads();
    }
    if (i < n) data[i] = s[t];
    if (t == SCAN_B - 1) bsum[blk] = s[t];
}

// Scan phase 2 (fused): each block computes its own prefix over the block
// sums (block reduce over <=512 ints), adds it, and initializes the cursor.
__global__ void scan_add(int nb1, int n1, int n2) {
    __shared__ int sb[SCAN_B];
    int sel = (blockIdx.x >= nb1) ? 1 : 0;
    int blk = sel ? blockIdx.x - nb1 : blockIdx.x;
    int n   = sel ? n2 : n1;
    int* data = sel ? g_off2 : g_off1;
    int* cur  = sel ? g_cur2 : g_cur1;
    const int* bsum = sel ? g_bsum2 : g_bsum1;

    int t = threadIdx.x;
    int partial = 0;
    for (int j = t; j < blk; j += SCAN_B) partial += bsum[j];
    sb[t] = partial;
    __syncthreads();
#pragma unroll
    for (int d = SCAN_B / 2; d > 0; d >>= 1) {
        if (t < d) sb[t] += sb[t + d];
        __syncthreads();
    }
    int base = sb[0];

    int i = blk * SCAN_B + t;
    if (i < n) {
        int v = data[i] + base;
        data[i] = v;
        cur[i]  = v;
    }
}

__global__ void reorder_kernel(const int* __restrict__ s1, const int* __restrict__ d1, int E1,
                               const int* __restrict__ s2, const int* __restrict__ d2, int E2) {
    int i = blockIdx.x * blockDim.x + threadIdx.x;
    if (i < E1) {
        int p = atomicAdd(&g_cur1[__ldg(d1 + i)], 1);
        g_csr1[p] = __ldg(s1 + i);
    }
    if (i < E2) {
        int p = atomicAdd(&g_cur2[__ldg(d2 + i)], 1);
        g_csr2[p] = __ldg(s2 + i);
    }
}

// ---------------------------------------------------------------------------
// FUSED segment-mean + Linear. One block = 64 dst nodes of ONE relation.
// Phase A: 8 warps, warp w computes means of nodes [w*8, w*8+8). Each
//   half-warp (16 lanes x float4 = full 64-f32 row) takes a contiguous half
//   of the segment, unrolled x2 -> >=4 loads in flight. Mean -> smem.
// Phase B: block GEMM  out = Ms @ W^T + (deg>0 ? b : 0), W in smem,
//   4 passes of 16 rows x 64 cols, written straight to d_out.
// Grid: blocks [0, nbI) -> items (rel1), [nbI, nbI+nbU) -> users (rel2).
// ---------------------------------------------------------------------------
__global__ __launch_bounds__(256) void fused_kernel(
        const float4* __restrict__ feat1, const float4* __restrict__ feat2,
        const float4* __restrict__ W1, const float* __restrict__ b1,
        const float4* __restrict__ W2, const float* __restrict__ b2,
        float* __restrict__ out_item, float* __restrict__ out_user,
        int nbI, int n_item, int n_user) {
    __shared__ float4 Ws[64][17];
    __shared__ float4 Ms[NODES_PER_BLK][17];
    __shared__ float  bs[64];
    __shared__ int    mk[NODES_PER_BLK];

    int sel = (blockIdx.x >= nbI) ? 1 : 0;
    int blk = sel ? blockIdx.x - nbI : blockIdx.x;
    const int*    csr  = sel ? g_csr2 : g_csr1;
    const int*    off  = sel ? g_off2 : g_off1;
    const float4* feat = sel ? feat2 : feat1;
    const float4* W    = sel ? W2 : W1;
    const float*  b    = sel ? b2 : b1;
    float*        out  = sel ? out_user : out_item;
    int           N    = sel ? n_user : n_item;

    int tid  = threadIdx.x;
    int wid  = tid >> 5;
    int lane = tid & 31;
    int node0 = blk * NODES_PER_BLK;

    // Load W (64 rows x 16 float4) and bias
    for (int i = tid; i < 64 * 16; i += 256) Ws[i >> 4][i & 15] = W[i];
    if (tid < 64) bs[tid] = b[tid];

    // ---- Phase A: per-node segment means ----
    int half = lane >> 4, q = lane & 15;
#pragma unroll
    for (int j = 0; j < 8; j++) {
        int local = wid * 8 + j;
        int node  = node0 + local;

        float4 a0 = make_float4(0.f, 0.f, 0.f, 0.f);
        float4 a1 = make_float4(0.f, 0.f, 0.f, 0.f);
        int cnt = 0;

        if (node < N) {
            int beg = __ldg(off + node), end = __ldg(off + node + 1);
            cnt = end - beg;
            int c0  = (cnt + 1) >> 1;                  // half 0: ceil, half 1: rest
            int myb = beg + (half ? c0 : 0);
            int myc = half ? (cnt - c0) : c0;

            int i = 0;
            for (; i + 2 <= myc; i += 2) {
                int s0 = __ldg(csr + myb + i);
                int s1 = __ldg(csr + myb + i + 1);
                float4 v0 = __ldg(feat + (long long)s0 * 16 + q);
                float4 v1 = __ldg(feat + (long long)s1 * 16 + q);
                a0.x += v0.x; a0.y += v0.y; a0.z += v0.z; a0.w += v0.w;
                a1.x += v1.x; a1.y += v1.y; a1.z += v1.z; a1.w += v1.w;
            }
            if (i < myc) {
                int s0 = __ldg(csr + myb + i);
                float4 v0 = __ldg(feat + (long long)s0 * 16 + q);
                a0.x += v0.x; a0.y += v0.y; a0.z += v0.z; a0.w += v0.w;
            }
        }

        a0.x += a1.x; a0.y += a1.y; a0.z += a1.z; a0.w += a1.w;
        a0.x += __shfl_xor_sync(0xffffffffu, a0.x, 16);
        a0.y += __shfl_xor_sync(0xffffffffu, a0.y, 16);
        a0.z += __shfl_xor_sync(0xffffffffu, a0.z, 16);
        a0.w += __shfl_xor_sync(0xffffffffu, a0.w, 16);

        float inv = (cnt > 0) ? 1.0f / (float)cnt : 0.0f;
        if (lane < 16) {
            a0.x *= inv; a0.y *= inv; a0.z *= inv; a0.w *= inv;
            Ms[local][q] = a0;
        }
        if (lane == 0) mk[local] = (cnt > 0);
    }
    __syncthreads();

    // ---- Phase B: out = Ms @ W^T + mask*b ----
    int c    = tid & 63;
    int rsub = tid >> 6;            // 0..3

#pragma unroll
    for (int pass = 0; pass < 4; pass++) {
        int lr = pass * 16 + 4 * rsub;   // local row base (4 rows per thread)

        float acc0 = mk[lr + 0] ? bs[c] : 0.f;
        float acc1 = mk[lr + 1] ? bs[c] : 0.f;
        float acc2 = mk[lr + 2] ? bs[c] : 0.f;
        float acc3 = mk[lr + 3] ? bs[c] : 0.f;

#pragma unroll
        for (int k = 0; k < 16; k++) {
            float4 w  = Ws[c][k];
            float4 x0 = Ms[lr + 0][k];
            float4 x1 = Ms[lr + 1][k];
            float4 x2 = Ms[lr + 2][k];
            float4 x3 = Ms[lr + 3][k];
            acc0 += x0.x * w.x + x0.y * w.y + x0.z * w.z + x0.w * w.w;
            acc1 += x1.x * w.x + x1.y * w.y + x1.z * w.z + x1.w * w.w;
            acc2 += x2.x * w.x + x2.y * w.y + x2.z * w.z + x2.w * w.w;
            acc3 += x3.x * w.x + x3.y * w.y + x3.z * w.z + x3.w * w.w;
        }

        int rr = node0 + lr;
        if (rr + 0 < N) out[(long long)(rr + 0) * 64 + c] = acc0;
        if (rr + 1 < N) out[(long long)(rr + 1) * 64 + c] = acc1;
        if (rr + 2 < N) out[(long long)(rr + 2) * 64 + c] = acc2;
        if (rr + 3 < N) out[(long long)(rr + 3) * 64 + c] = acc3;
    }
}

// ---------------------------------------------------------------------------
extern "C" void kernel_launch(void* const* d_in, const int* in_sizes, int n_in,
                              void* d_out, int out_size) {
    const float* feat_user  = (const float*)d_in[0];
    const float* feat_item  = (const float*)d_in[1];
    const int*   src_clicks = (const int*)d_in[2];
    const int*   dst_clicks = (const int*)d_in[3];
    const int*   src_cb     = (const int*)d_in[4];
    const int*   dst_cb     = (const int*)d_in[5];
    const float* W_clicks   = (const float*)d_in[6];
    const float* b_clicks   = (const float*)d_in[7];
    const float* W_cb       = (const float*)d_in[8];
    const float* b_cb       = (const float*)d_in[9];

    int n_user = in_sizes[0] / 64;
    int n_item = in_sizes[1] / 64;
    int E1 = in_sizes[2];   // clicks edges      (user -> item)
    int E2 = in_sizes[4];   // clicked_by edges  (item -> user)
    int Emax = E1 > E2 ? E1 : E2;

    float* out_user = (float*)d_out;                         // [n_user, 64]
    float* out_item = out_user + (long long)n_user * 64;     // [n_item, 64]

    int n1 = n_item + 1, n2 = n_user + 1;
    int nb1 = (n1 + SCAN_B - 1) / SCAN_B;
    int nb2 = (n2 + SCAN_B - 1) / SCAN_B;
    int nmax = n_item > n_user ? n_item : n_user;

    // 1. zero counters
    zero_cnt<<<(nmax + 1 + 255) / 256, 256>>>(n_item, n_user);
    // 2. histogram (both relations)
    hist_kernel<<<(Emax + 255) / 256, 256>>>(dst_clicks, E1, dst_cb, E2);
    // 3-4. scan (both relations per launch; phase 2 self-computes block prefix)
    scan_block<<<nb1 + nb2, SCAN_B>>>(nb1, n1, n2);
    scan_add<<<nb1 + nb2, SCAN_B>>>(nb1, n1, n2);
    // 5. reorder (both relations)
    reorder_kernel<<<(Emax + 255) / 256, 256>>>(src_clicks, dst_clicks, E1,
                                                src_cb, dst_cb, E2);
    // 6. fused segment-mean + Linear -> d_out (both relations)
    {
        int nbI = (n_item + NODES_PER_BLK - 1) / NODES_PER_BLK;
        int nbU = (n_user + NODES_PER_BLK - 1) / NODES_PER_BLK;
        fused_kernel<<<nbI + nbU, 256>>>((const float4*)feat_user,
                                         (const float4*)feat_item,
                                         (const float4*)W_clicks, b_clicks,
                                         (const float4*)W_cb, b_cb,
                                         out_item, out_user,
                                         nbI, n_item, n_user);
    }
}